// round 13
// baseline (speedup 1.0000x reference)
#include <cuda_runtime.h>
#include <cuda_fp16.h>
#include <cstdint>
#include <cstddef>

namespace {

constexpr int Nc = 16384, Kc = 32, Dc = 64;
constexpr int POINTS = 4 * Nc;           // 65536
constexpr int NTHR   = 128;              // 4 warps / CTA
constexpr int NCTA   = 740;              // 5 CTAs / SM, one full wave

// ---- shared memory layout (byte offsets) ----
constexpr int SM_BFRAG = 0;              // W2 fp16 fragment table: 4*8*32*8 = 8192 B
constexpr int SM_W1Q   = 8192;           // packed W1/b1 col-pair table: 32*32 = 1024 B
constexpr int SM_B2T   = 9216;           // b2 fp16x2 fragment table: 4*8*4 = 128 B
constexpr int SM_WARP  = 9344;           // 4 per-warp Gs16 regions
constexpr int PW       = 4608;           // Gs16 [32 x 144B]
constexpr int SMEM_BYTES = SM_WARP + 4 * PW;   // 27776
constexpr int GSTRIDE = 144;

__device__ __forceinline__ uint32_t smem_u32(const void* p) {
    uint32_t a;
    asm("{ .reg .u64 t; cvta.to.shared.u64 t, %1; cvt.u32.u64 %0, t; }" : "=r"(a) : "l"(p));
    return a;
}
__device__ __forceinline__ uint32_t pack_h2(__half lo, __half hi) {
    return (uint32_t)__half_as_ushort(lo) | ((uint32_t)__half_as_ushort(hi) << 16);
}
__device__ __forceinline__ unsigned long long pack_f2(float lo, float hi) {
    unsigned long long d;
    asm("mov.b64 %0, {%1, %2};" : "=l"(d) : "f"(lo), "f"(hi));
    return d;
}
__device__ __forceinline__ unsigned long long ffma2(unsigned long long a,
                                                    unsigned long long b,
                                                    unsigned long long c) {
    unsigned long long d;
    asm("fma.rn.f32x2 %0, %1, %2, %3;" : "=l"(d) : "l"(a), "l"(b), "l"(c));
    return d;
}
__device__ __forceinline__ unsigned long long fmul2(unsigned long long a,
                                                    unsigned long long b) {
    unsigned long long d;
    asm("mul.rn.f32x2 %0, %1, %2;" : "=l"(d) : "l"(a), "l"(b));
    return d;
}
__device__ __forceinline__ uint32_t cvt_f16x2(unsigned long long zpair) {
    uint32_t lo, hi, d;
    asm("mov.b64 {%0, %1}, %2;" : "=r"(lo), "=r"(hi) : "l"(zpair));
    asm("cvt.rn.f16x2.f32 %0, %1, %2;" : "=r"(d)
        : "f"(__uint_as_float(hi)), "f"(__uint_as_float(lo)));
    return d;
}
__device__ __forceinline__ unsigned long long abs2(unsigned long long a) {
    uint32_t lo, hi;
    asm("mov.b64 {%0, %1}, %2;" : "=r"(lo), "=r"(hi) : "l"(a));
    lo &= 0x7FFFFFFFu; hi &= 0x7FFFFFFFu;
    unsigned long long d;
    asm("mov.b64 %0, {%1, %2};" : "=l"(d) : "r"(lo), "r"(hi));
    return d;
}
// fp16-accumulate HMMA: C/D fragment = 2 regs of fp16x2
__device__ __forceinline__ void mma_f16_h(uint32_t* c, const uint32_t* a,
                                          uint32_t b0, uint32_t b1) {
    asm volatile(
        "mma.sync.aligned.m16n8k16.row.col.f16.f16.f16.f16 "
        "{%0,%1}, {%2,%3,%4,%5}, {%6,%7}, {%0,%1};"
        : "+r"(c[0]), "+r"(c[1])
        : "r"(a[0]), "r"(a[1]), "r"(a[2]), "r"(a[3]), "r"(b0), "r"(b1));
}
// one fragment reg: fp16x2 of leaky(rel . W1[:,c0..c0+1] + b1) for one row
__device__ __forceinline__ uint32_t frag_pair(
    unsigned long long rpx, unsigned long long rpy, unsigned long long rpz,
    unsigned long long wx, unsigned long long wy, unsigned long long wz,
    unsigned long long bb,
    unsigned long long c055, unsigned long long c045) {
    unsigned long long z = ffma2(rpx, wx, ffma2(rpy, wy, ffma2(rpz, wz, bb)));
    z = ffma2(abs2(z), c045, fmul2(z, c055));   // leaky = 0.55 z + 0.45 |z|
    return cvt_f16x2(z);
}

} // namespace

// x pre-converted to fp16 (8 MB static scratch; written by cvt_x_kernel)
__device__ __half2 g_xh[(size_t)4 * 16384 * 32];

__global__ void cvt_x_kernel(const float* __restrict__ x) {
    const int i = blockIdx.x * blockDim.x + threadIdx.x;   // 2,097,152 threads
    const float2 v = ((const float2*)x)[i];
    g_xh[i] = __floats2half2_rn(v.x, v.y);
}

__global__ void __launch_bounds__(NTHR, 5) pc_mma_kernel(
    const float* __restrict__ pos,    // [B, N, 3]
    const int*   __restrict__ nidx,   // [B, N, 32]
    const float* __restrict__ W1,     // [3, 64]
    const float* __restrict__ b1,     // [64]
    const float* __restrict__ W2,     // [64, 64]
    const float* __restrict__ b2,     // [64]
    float*       __restrict__ out)    // [B, N, 64]
{
    extern __shared__ char smem[];
    const uint32_t sb = smem_u32(smem);

    const int tid  = threadIdx.x;
    const int warp = tid >> 5;
    const int lane = tid & 31;
    const int f0   = 2 * lane;
    const int q    = lane >> 2;       // fragment row base
    const int r    = lane & 3;        // fragment col-pair selector

    // ================= one-time init =================
    // W2'' fp16 fragment table (single plane), entry (s, ni, ln) = 8B {b0, b1}
    for (int i = tid; i < 4 * 8 * 32; i += NTHR) {
        const int s = i >> 8, ni = (i >> 5) & 7, ln = i & 31;
        const int n  = ni * 8 + (ln >> 2);
        const int k0 = s * 16 + (ln & 3) * 2;
        uint2 e;
        e.x = pack_h2(__float2half_rn(W2[k0 * Dc + n]),
                      __float2half_rn(W2[(k0 + 1) * Dc + n]));
        e.y = pack_h2(__float2half_rn(W2[(k0 + 8) * Dc + n]),
                      __float2half_rn(W2[(k0 + 9) * Dc + n]));
        *(uint2*)(smem + SM_BFRAG + (size_t)i * 8) = e;
    }
    // W1/b1 col-pair table: entry e = (s*2+d)*4 + r, 32B:
    //   {W1[0][c0],W1[0][c0+1]} {W1[1][..]} {W1[2][..]} {b1[..]},  c0=16s+2r+8d
    for (int e = tid; e < 32; e += NTHR) {
        const int er = e & 3, ed = (e >> 2) & 1, es = e >> 3;
        const int c0 = 16 * es + 2 * er + 8 * ed;
        float2* dst = (float2*)(smem + SM_W1Q + (size_t)e * 32);
        dst[0] = make_float2(W1[c0],          W1[c0 + 1]);
        dst[1] = make_float2(W1[Dc + c0],     W1[Dc + c0 + 1]);
        dst[2] = make_float2(W1[2 * Dc + c0], W1[2 * Dc + c0 + 1]);
        dst[3] = make_float2(b1[c0],          b1[c0 + 1]);
    }
    // b2 fp16x2 fragment table: entry (rr, ni) = pack(b2[ni*8+2rr], b2[ni*8+2rr+1])
    for (int e = tid; e < 32; e += NTHR) {
        const int rr = e >> 3, ni = e & 7;
        ((uint32_t*)(smem + SM_B2T))[rr * 8 + ni] =
            pack_h2(__float2half_rn(b2[ni * 8 + 2 * rr]),
                    __float2half_rn(b2[ni * 8 + 2 * rr + 1]));
    }
    __syncthreads();

    // ================= per-lane constants =================
    const uint32_t wbase = sb + SM_WARP + warp * PW;          // Gs16 region
    const uint32_t bfrag_base = sb + SM_BFRAG + (uint32_t)lane * 8u;
    const uint32_t w1q_base = sb + SM_W1Q + (uint32_t)r * 32u;
    const uint32_t b2t_base = sb + SM_B2T + (uint32_t)r * 32u;

    const int pstride = NCTA * 4;

    // ---- prefetch state for point p ----
    int p = blockIdx.x * 4 + warp;
    int   jv = 0;
    float cxv = 0.f, cyv = 0.f, czv = 0.f, nxv = 0.f, nyv = 0.f, nzv = 0.f;
    if (p < POINTS) {
        const int bb = p >> 14;
        jv  = nidx[(size_t)p * Kc + lane];
        cxv = pos[(size_t)p * 3 + 0];
        cyv = pos[(size_t)p * 3 + 1];
        czv = pos[(size_t)p * 3 + 2];
        const float* npp = pos + (size_t)(bb * Nc + jv) * 3;
        nxv = npp[0]; nyv = npp[1]; nzv = npp[2];
    }

    for (; p < POINTS; p += pstride) {
        const int b = p >> 14;
        const int j = jv;
        const float rx = cxv - nxv, ry = cyv - nyv, rz = czv - nzv;

        // ---- rel for this lane's 4 fragment rows, kept as scalars ----
        float fx[4], fy[4], fz[4];
#pragma unroll
        for (int i = 0; i < 4; ++i) {
            const int src = q + 8 * i;
            fx[i] = __shfl_sync(0xFFFFFFFFu, rx, src);
            fy[i] = __shfl_sync(0xFFFFFFFFu, ry, src);
            fz[i] = __shfl_sync(0xFFFFFFFFu, rz, src);
        }

        // ---- prefetch next point's idx/pos (consumed next iteration) ----
        {
            const int pn = p + pstride;
            if (pn < POINTS) {
                const int bn = pn >> 14;
                jv  = nidx[(size_t)pn * Kc + lane];
                cxv = pos[(size_t)pn * 3 + 0];
                cyv = pos[(size_t)pn * 3 + 1];
                czv = pos[(size_t)pn * 3 + 2];
                const float* npp = pos + (size_t)(bn * Nc + jv) * 3;
                nxv = npp[0]; nyv = npp[1]; nzv = npp[2];
            }
        }

        // ---- GEMM (fp16 acc), acc init = b2 -> G' = H*W2 + b2 in fp16x2 ----
        uint32_t acc[32];
        {
            uint32_t bt[8];
            asm("ld.shared.v4.u32 {%0,%1,%2,%3}, [%4];"
                : "=r"(bt[0]), "=r"(bt[1]), "=r"(bt[2]), "=r"(bt[3]) : "r"(b2t_base));
            asm("ld.shared.v4.u32 {%0,%1,%2,%3}, [%4];"
                : "=r"(bt[4]), "=r"(bt[5]), "=r"(bt[6]), "=r"(bt[7]) : "r"(b2t_base + 16));
#pragma unroll
            for (int ni = 0; ni < 8; ++ni) {
                acc[ni * 4 + 0] = bt[ni];
                acc[ni * 4 + 1] = bt[ni];
                acc[ni * 4 + 2] = bt[ni];
                acc[ni * 4 + 3] = bt[ni];
            }
        }

#pragma unroll
        for (int s = 0; s < 4; ++s) {
            const unsigned long long c055 = pack_f2(0.55f, 0.55f);
            const unsigned long long c045 = pack_f2(0.45f, 0.45f);

            unsigned long long wx0, wy0, wz0, bb0, wx1, wy1, wz1, bb1;
            const uint32_t qa = w1q_base + (uint32_t)(s * 256);
            asm("ld.shared.v2.b64 {%0,%1}, [%2];" : "=l"(wx0), "=l"(wy0) : "r"(qa));
            asm("ld.shared.v2.b64 {%0,%1}, [%2];" : "=l"(wz0), "=l"(bb0) : "r"(qa + 16));
            asm("ld.shared.v2.b64 {%0,%1}, [%2];" : "=l"(wx1), "=l"(wy1) : "r"(qa + 128));
            asm("ld.shared.v2.b64 {%0,%1}, [%2];" : "=l"(wz1), "=l"(bb1) : "r"(qa + 144));

            uint32_t at0[4], at1[4];
            {
                const unsigned long long r0x = pack_f2(fx[0], fx[0]);
                const unsigned long long r0y = pack_f2(fy[0], fy[0]);
                const unsigned long long r0z = pack_f2(fz[0], fz[0]);
                const unsigned long long r1x = pack_f2(fx[1], fx[1]);
                const unsigned long long r1y = pack_f2(fy[1], fy[1]);
                const unsigned long long r1z = pack_f2(fz[1], fz[1]);
                at0[0] = frag_pair(r0x, r0y, r0z, wx0, wy0, wz0, bb0, c055, c045);
                at0[1] = frag_pair(r1x, r1y, r1z, wx0, wy0, wz0, bb0, c055, c045);
                at0[2] = frag_pair(r0x, r0y, r0z, wx1, wy1, wz1, bb1, c055, c045);
                at0[3] = frag_pair(r1x, r1y, r1z, wx1, wy1, wz1, bb1, c055, c045);
            }
            {
                const unsigned long long r2x = pack_f2(fx[2], fx[2]);
                const unsigned long long r2y = pack_f2(fy[2], fy[2]);
                const unsigned long long r2z = pack_f2(fz[2], fz[2]);
                const unsigned long long r3x = pack_f2(fx[3], fx[3]);
                const unsigned long long r3y = pack_f2(fy[3], fy[3]);
                const unsigned long long r3z = pack_f2(fz[3], fz[3]);
                at1[0] = frag_pair(r2x, r2y, r2z, wx0, wy0, wz0, bb0, c055, c045);
                at1[1] = frag_pair(r3x, r3y, r3z, wx0, wy0, wz0, bb0, c055, c045);
                at1[2] = frag_pair(r2x, r2y, r2z, wx1, wy1, wz1, bb1, c055, c045);
                at1[3] = frag_pair(r3x, r3y, r3z, wx1, wy1, wz1, bb1, c055, c045);
            }

            const uint32_t bptr = bfrag_base + (uint32_t)s * 2048u;
#pragma unroll
            for (int ni = 0; ni < 8; ++ni) {
                uint32_t h0, h1;
                asm volatile("ld.shared.v2.u32 {%0,%1}, [%2];"
                             : "=r"(h0), "=r"(h1) : "r"(bptr + ni * 256u));
                mma_f16_h(&acc[ni * 4],     at0, h0, h1);
                mma_f16_h(&acc[ni * 4 + 2], at1, h0, h1);
            }
        }

        // ---- transpose G' to Gs16 [32 rows x 144B] (regs already fp16x2) ----
        {
            const uint32_t gdst = wbase + (uint32_t)(r * 4 + q * GSTRIDE);
#pragma unroll
            for (int ni = 0; ni < 8; ++ni) {
                const uint32_t a = gdst + (uint32_t)(ni * 16);
                asm volatile("st.shared.b32 [%0], %1;" :: "r"(a),                 "r"(acc[ni * 4 + 0]));
                asm volatile("st.shared.b32 [%0], %1;" :: "r"(a + 8 * GSTRIDE),   "r"(acc[ni * 4 + 1]));
                asm volatile("st.shared.b32 [%0], %1;" :: "r"(a + 16 * GSTRIDE),  "r"(acc[ni * 4 + 2]));
                asm volatile("st.shared.b32 [%0], %1;" :: "r"(a + 24 * GSTRIDE),  "r"(acc[ni * 4 + 3]));
            }
        }
        __syncwarp();

        // ---- epilogue: out[f] = sum_k G'[k,f] * x_h[j_k, f]  (fp16 product) ----
        const __half2* xhb = g_xh + (size_t)b * Nc * 32;
        const uint32_t gsrc = wbase + (uint32_t)lane * 4u;
        float o0 = 0.0f, o1 = 0.0f;
#pragma unroll
        for (int kb = 0; kb < 4; ++kb) {
            __half2 xv[8];
#pragma unroll
            for (int u = 0; u < 8; ++u) {
                const int jk = __shfl_sync(0xFFFFFFFFu, j, kb * 8 + u);
                xv[u] = xhb[(size_t)jk * 32 + lane];
            }
#pragma unroll
            for (int u = 0; u < 8; ++u) {
                uint32_t gv;
                asm volatile("ld.shared.b32 %0, [%1];"
                             : "=r"(gv) : "r"(gsrc + (uint32_t)((kb * 8 + u) * GSTRIDE)));
                const __half2 prod = __hmul2(*(const __half2*)&gv, xv[u]);
                const float2 pf = __half22float2(prod);
                o0 += pf.x;
                o1 += pf.y;
            }
        }
        __syncwarp();   // Gs region reused next iteration

        *(float2*)(out + (size_t)p * Dc + f0) = make_float2(o0, o1);
    }
}

extern "C" void kernel_launch(void* const* d_in, const int* in_sizes, int n_in,
                              void* d_out, int out_size) {
    const float* x    = (const float*)d_in[0];
    const float* pos  = (const float*)d_in[1];
    const int*   nidx = (const int*)  d_in[2];
    const float* W1   = (const float*)d_in[3];
    const float* b1   = (const float*)d_in[4];
    const float* W2   = (const float*)d_in[5];
    const float* b2   = (const float*)d_in[6];
    float* out = (float*)d_out;
    (void)in_sizes; (void)n_in; (void)out_size;

    // x -> fp16 scratch (4*16384*64 floats = 2,097,152 half2)
    cvt_x_kernel<<<8192, 256>>>(x);

    cudaFuncSetAttribute(pc_mma_kernel, cudaFuncAttributeMaxDynamicSharedMemorySize,
                         SMEM_BYTES);
    pc_mma_kernel<<<NCTA, NTHR, SMEM_BYTES>>>(pos, nidx, W1, b1, W2, b2, out);
}

// round 14
// speedup vs baseline: 1.1102x; 1.1102x over previous
#include <cuda_runtime.h>
#include <cuda_fp16.h>
#include <cstdint>
#include <cstring>
#include <cstddef>

namespace {

constexpr int Nc = 16384, Kc = 32, Dc = 64;
constexpr int POINTS = 4 * Nc;           // 65536
constexpr int NTHR   = 128;              // 4 warps / CTA
constexpr int NCTA   = 740;              // 5 CTAs / SM, one full wave

// ---- shared memory layout (byte offsets) ----
constexpr int SM_BFRAG = 0;              // W2 fp16 fragment table: 4*8*32*8 = 8192 B
constexpr int SM_W1Q   = 8192;           // fp16 W1/b1 col-pair table: 32*16 = 512 B
constexpr int SM_B2T   = 9216;           // b2 fp16x2 fragment table: 128 B
constexpr int SM_WARP  = 9344;           // 4 per-warp Gs16 regions
constexpr int PW       = 4608;           // Gs16: 16 row-pairs x 288 B
constexpr int SMEM_BYTES = SM_WARP + 4 * PW;   // 27776
constexpr int GPS = 288;                 // bytes per interleaved row-pair

__device__ __forceinline__ uint32_t smem_u32(const void* p) {
    uint32_t a;
    asm("{ .reg .u64 t; cvta.to.shared.u64 t, %1; cvt.u32.u64 %0, t; }" : "=r"(a) : "l"(p));
    return a;
}
__device__ __forceinline__ uint32_t pack_h2(__half lo, __half hi) {
    return (uint32_t)__half_as_ushort(lo) | ((uint32_t)__half_as_ushort(hi) << 16);
}
__device__ __forceinline__ uint32_t h2_u32(__half2 h) {
    uint32_t u; memcpy(&u, &h, 4); return u;
}
__device__ __forceinline__ __half2 u32_h2(uint32_t u) {
    __half2 h; memcpy(&h, &u, 4); return h;
}
// fp16-accumulate HMMA: C/D fragment = 2 regs of fp16x2
__device__ __forceinline__ void mma_f16_h(uint32_t* c, const uint32_t* a,
                                          uint32_t b0, uint32_t b1) {
    asm volatile(
        "mma.sync.aligned.m16n8k16.row.col.f16.f16.f16.f16 "
        "{%0,%1}, {%2,%3,%4,%5}, {%6,%7}, {%0,%1};"
        : "+r"(c[0]), "+r"(c[1])
        : "r"(a[0]), "r"(a[1]), "r"(a[2]), "r"(a[3]), "r"(b0), "r"(b1));
}
// one A-fragment reg, entirely in fp16x2:
//   z = rel.W1[:,c0..c0+1] + b1;  leaky = max(z, 0.1*z)
__device__ __forceinline__ uint32_t frag_h(uint32_t rx2, uint32_t ry2, uint32_t rz2,
                                           uint32_t wx, uint32_t wy, uint32_t wz,
                                           uint32_t bb, __half2 c01) {
    __half2 z = __hfma2(u32_h2(rx2), u32_h2(wx),
                __hfma2(u32_h2(ry2), u32_h2(wy),
                __hfma2(u32_h2(rz2), u32_h2(wz), u32_h2(bb))));
    z = __hmax2(z, __hmul2(z, c01));
    return h2_u32(z);
}

} // namespace

// x pre-converted to fp16 (8 MB static scratch; written by cvt_x_kernel)
__device__ __half2 g_xh[(size_t)4 * 16384 * 32];

__global__ void cvt_x_kernel(const float* __restrict__ x) {
    const int i = blockIdx.x * blockDim.x + threadIdx.x;   // 2,097,152 threads
    const float2 v = ((const float2*)x)[i];
    g_xh[i] = __floats2half2_rn(v.x, v.y);
}

__global__ void __launch_bounds__(NTHR, 5) pc_mma_kernel(
    const float* __restrict__ pos,    // [B, N, 3]
    const int*   __restrict__ nidx,   // [B, N, 32]
    const float* __restrict__ W1,     // [3, 64]
    const float* __restrict__ b1,     // [64]
    const float* __restrict__ W2,     // [64, 64]
    const float* __restrict__ b2,     // [64]
    float*       __restrict__ out)    // [B, N, 64]
{
    extern __shared__ char smem[];
    const uint32_t sb = smem_u32(smem);

    const int tid  = threadIdx.x;
    const int warp = tid >> 5;
    const int lane = tid & 31;
    const int f0   = 2 * lane;
    const int q    = lane >> 2;       // fragment row base
    const int r    = lane & 3;        // fragment col-pair selector

    // ================= one-time init =================
    // W2'' fp16 fragment table (single plane), entry (s, ni, ln) = 8B {b0, b1}
    for (int i = tid; i < 4 * 8 * 32; i += NTHR) {
        const int s = i >> 8, ni = (i >> 5) & 7, ln = i & 31;
        const int n  = ni * 8 + (ln >> 2);
        const int k0 = s * 16 + (ln & 3) * 2;
        uint2 e;
        e.x = pack_h2(__float2half_rn(W2[k0 * Dc + n]),
                      __float2half_rn(W2[(k0 + 1) * Dc + n]));
        e.y = pack_h2(__float2half_rn(W2[(k0 + 8) * Dc + n]),
                      __float2half_rn(W2[(k0 + 9) * Dc + n]));
        *(uint2*)(smem + SM_BFRAG + (size_t)i * 8) = e;
    }
    // fp16 W1/b1 col-pair table: entry e = (s*2+d)*4 + r, 16B {wx, wy, wz, bb}
    //   c0 = 16s + 2r + 8d; wx = {f16 W1[0][c0], f16 W1[0][c0+1]}, ...
    for (int e = tid; e < 32; e += NTHR) {
        const int er = e & 3, ed = (e >> 2) & 1, es = e >> 3;
        const int c0 = 16 * es + 2 * er + 8 * ed;
        uint4 v;
        v.x = pack_h2(__float2half_rn(W1[c0]),          __float2half_rn(W1[c0 + 1]));
        v.y = pack_h2(__float2half_rn(W1[Dc + c0]),     __float2half_rn(W1[Dc + c0 + 1]));
        v.z = pack_h2(__float2half_rn(W1[2 * Dc + c0]), __float2half_rn(W1[2 * Dc + c0 + 1]));
        v.w = pack_h2(__float2half_rn(b1[c0]),          __float2half_rn(b1[c0 + 1]));
        ((uint4*)(smem + SM_W1Q))[e] = v;
    }
    // b2 fp16x2 fragment table: entry (rr, ni) = pack(b2[ni*8+2rr], b2[ni*8+2rr+1])
    for (int e = tid; e < 32; e += NTHR) {
        const int rr = e >> 3, ni = e & 7;
        ((uint32_t*)(smem + SM_B2T))[rr * 8 + ni] =
            pack_h2(__float2half_rn(b2[ni * 8 + 2 * rr]),
                    __float2half_rn(b2[ni * 8 + 2 * rr + 1]));
    }
    __syncthreads();

    // ================= per-lane constants =================
    const uint32_t wbase = sb + SM_WARP + warp * PW;          // Gs16 region
    const uint32_t bfrag_base = sb + SM_BFRAG + (uint32_t)lane * 8u;
    const uint32_t w1q_base = sb + SM_W1Q + (uint32_t)r * 16u;
    const uint32_t b2t_base = sb + SM_B2T + (uint32_t)r * 32u;
    // Gs store base: row-pair interleaved (row -> pair row>>1, parity (row&1)*4)
    const uint32_t gdst0 = wbase + (uint32_t)((q >> 1) * GPS + (q & 1) * 4 + r * 8);
    const uint32_t gsrc  = wbase + (uint32_t)lane * 8u;
    const __half2 c01 = __float2half2_rn(0.1f);

    const int pstride = NCTA * 4;

    // ---- prefetch state for point p ----
    int p = blockIdx.x * 4 + warp;
    int   jv = 0;
    float cxv = 0.f, cyv = 0.f, czv = 0.f, nxv = 0.f, nyv = 0.f, nzv = 0.f;
    if (p < POINTS) {
        const int bb = p >> 14;
        jv  = nidx[(size_t)p * Kc + lane];
        cxv = pos[(size_t)p * 3 + 0];
        cyv = pos[(size_t)p * 3 + 1];
        czv = pos[(size_t)p * 3 + 2];
        const float* npp = pos + (size_t)(bb * Nc + jv) * 3;
        nxv = npp[0]; nyv = npp[1]; nzv = npp[2];
    }

    for (; p < POINTS; p += pstride) {
        const int b = p >> 14;
        const int j = jv;
        const float rx = cxv - nxv, ry = cyv - nyv, rz = czv - nzv;

        // ---- rel as broadcast fp16x2, for this lane's 4 fragment rows ----
        const uint32_t urx = h2_u32(__float2half2_rn(rx));
        const uint32_t ury = h2_u32(__float2half2_rn(ry));
        const uint32_t urz = h2_u32(__float2half2_rn(rz));
        uint32_t rpx[4], rpy[4], rpz[4];
#pragma unroll
        for (int i = 0; i < 4; ++i) {
            const int src = q + 8 * i;
            rpx[i] = __shfl_sync(0xFFFFFFFFu, urx, src);
            rpy[i] = __shfl_sync(0xFFFFFFFFu, ury, src);
            rpz[i] = __shfl_sync(0xFFFFFFFFu, urz, src);
        }

        // ---- prefetch next point's idx/pos (consumed next iteration) ----
        {
            const int pn = p + pstride;
            if (pn < POINTS) {
                const int bn = pn >> 14;
                jv  = nidx[(size_t)pn * Kc + lane];
                cxv = pos[(size_t)pn * 3 + 0];
                cyv = pos[(size_t)pn * 3 + 1];
                czv = pos[(size_t)pn * 3 + 2];
                const float* npp = pos + (size_t)(bn * Nc + jv) * 3;
                nxv = npp[0]; nyv = npp[1]; nzv = npp[2];
            }
        }

        // ---- GEMM (fp16 acc), acc init = b2 -> G' = H*W2 + b2 in fp16x2 ----
        uint32_t acc[32];
        {
            uint32_t bt[8];
            asm("ld.shared.v4.u32 {%0,%1,%2,%3}, [%4];"
                : "=r"(bt[0]), "=r"(bt[1]), "=r"(bt[2]), "=r"(bt[3]) : "r"(b2t_base));
            asm("ld.shared.v4.u32 {%0,%1,%2,%3}, [%4];"
                : "=r"(bt[4]), "=r"(bt[5]), "=r"(bt[6]), "=r"(bt[7]) : "r"(b2t_base + 16));
#pragma unroll
            for (int ni = 0; ni < 8; ++ni) {
                acc[ni * 4 + 0] = bt[ni];
                acc[ni * 4 + 1] = bt[ni];
                acc[ni * 4 + 2] = bt[ni];
                acc[ni * 4 + 3] = bt[ni];
            }
        }

#pragma unroll
        for (int s = 0; s < 4; ++s) {
            uint32_t w0[4], w1r[4];   // d=0 / d=1 col-pair weights {wx,wy,wz,bb}
            const uint32_t qa = w1q_base + (uint32_t)(s * 128);
            asm("ld.shared.v4.u32 {%0,%1,%2,%3}, [%4];"
                : "=r"(w0[0]), "=r"(w0[1]), "=r"(w0[2]), "=r"(w0[3]) : "r"(qa));
            asm("ld.shared.v4.u32 {%0,%1,%2,%3}, [%4];"
                : "=r"(w1r[0]), "=r"(w1r[1]), "=r"(w1r[2]), "=r"(w1r[3]) : "r"(qa + 64));

            uint32_t at0[4], at1[4];
            at0[0] = frag_h(rpx[0], rpy[0], rpz[0], w0[0], w0[1], w0[2], w0[3], c01);
            at0[1] = frag_h(rpx[1], rpy[1], rpz[1], w0[0], w0[1], w0[2], w0[3], c01);
            at0[2] = frag_h(rpx[0], rpy[0], rpz[0], w1r[0], w1r[1], w1r[2], w1r[3], c01);
            at0[3] = frag_h(rpx[1], rpy[1], rpz[1], w1r[0], w1r[1], w1r[2], w1r[3], c01);
            at1[0] = frag_h(rpx[2], rpy[2], rpz[2], w0[0], w0[1], w0[2], w0[3], c01);
            at1[1] = frag_h(rpx[3], rpy[3], rpz[3], w0[0], w0[1], w0[2], w0[3], c01);
            at1[2] = frag_h(rpx[2], rpy[2], rpz[2], w1r[0], w1r[1], w1r[2], w1r[3], c01);
            at1[3] = frag_h(rpx[3], rpy[3], rpz[3], w1r[0], w1r[1], w1r[2], w1r[3], c01);

            const uint32_t bptr = bfrag_base + (uint32_t)s * 2048u;
#pragma unroll
            for (int ni = 0; ni < 8; ++ni) {
                uint32_t h0, h1;
                asm volatile("ld.shared.v2.u32 {%0,%1}, [%2];"
                             : "=r"(h0), "=r"(h1) : "r"(bptr + ni * 256u));
                mma_f16_h(&acc[ni * 4],     at0, h0, h1);
                mma_f16_h(&acc[ni * 4 + 2], at1, h0, h1);
            }
        }

        // ---- transpose G' to pair-interleaved Gs16 (regs already fp16x2) ----
        // acc[ni*4 + m] = row q + 8m, colpair ni*4+r -> gdst0 + ni*32 + m*4*GPS
        {
#pragma unroll
            for (int ni = 0; ni < 8; ++ni) {
                const uint32_t a = gdst0 + (uint32_t)(ni * 32);
                asm volatile("st.shared.b32 [%0], %1;" :: "r"(a),               "r"(acc[ni * 4 + 0]));
                asm volatile("st.shared.b32 [%0], %1;" :: "r"(a + 4 * GPS),     "r"(acc[ni * 4 + 1]));
                asm volatile("st.shared.b32 [%0], %1;" :: "r"(a + 8 * GPS),     "r"(acc[ni * 4 + 2]));
                asm volatile("st.shared.b32 [%0], %1;" :: "r"(a + 12 * GPS),    "r"(acc[ni * 4 + 3]));
            }
        }
        __syncwarp();

        // ---- epilogue: out[f] = sum_k G'[k,f] * x_h[j_k, f]  (fp16 product) ----
        const __half2* xhb = g_xh + (size_t)b * Nc * 32;
        float o0 = 0.0f, o1 = 0.0f;
#pragma unroll
        for (int kb = 0; kb < 4; ++kb) {
            __half2 xv[8];
#pragma unroll
            for (int u = 0; u < 8; ++u) {
                const int jk = __shfl_sync(0xFFFFFFFFu, j, kb * 8 + u);
                xv[u] = xhb[(size_t)jk * 32 + lane];
            }
#pragma unroll
            for (int k2 = 0; k2 < 4; ++k2) {
                uint32_t g0, g1;   // rows 8kb + 2k2, 8kb + 2k2 + 1
                asm volatile("ld.shared.v2.u32 {%0,%1}, [%2];"
                             : "=r"(g0), "=r"(g1)
                             : "r"(gsrc + (uint32_t)((kb * 4 + k2) * GPS)));
                const __half2 p0 = __hmul2(u32_h2(g0), xv[k2 * 2]);
                const __half2 p1 = __hmul2(u32_h2(g1), xv[k2 * 2 + 1]);
                const float2 f0v = __half22float2(p0);
                const float2 f1v = __half22float2(p1);
                o0 += f0v.x + f1v.x;
                o1 += f0v.y + f1v.y;
            }
        }
        __syncwarp();   // Gs region reused next iteration

        *(float2*)(out + (size_t)p * Dc + f0) = make_float2(o0, o1);
    }
}

extern "C" void kernel_launch(void* const* d_in, const int* in_sizes, int n_in,
                              void* d_out, int out_size) {
    const float* x    = (const float*)d_in[0];
    const float* pos  = (const float*)d_in[1];
    const int*   nidx = (const int*)  d_in[2];
    const float* W1   = (const float*)d_in[3];
    const float* b1   = (const float*)d_in[4];
    const float* W2   = (const float*)d_in[5];
    const float* b2   = (const float*)d_in[6];
    float* out = (float*)d_out;
    (void)in_sizes; (void)n_in; (void)out_size;

    // x -> fp16 scratch (4*16384*64 floats = 2,097,152 half2)
    cvt_x_kernel<<<8192, 256>>>(x);

    cudaFuncSetAttribute(pc_mma_kernel, cudaFuncAttributeMaxDynamicSharedMemorySize,
                         SMEM_BYTES);
    pc_mma_kernel<<<NCTA, NTHR, SMEM_BYTES>>>(pos, nidx, W1, b1, W2, b2, out);
}

// round 15
// speedup vs baseline: 1.1133x; 1.0028x over previous
#include <cuda_runtime.h>
#include <cuda_fp16.h>
#include <cstdint>
#include <cstring>
#include <cstddef>

namespace {

constexpr int Nc = 16384, Kc = 32, Dc = 64;
constexpr int POINTS = 4 * Nc;           // 65536
constexpr int NTHR   = 128;              // 4 warps / CTA
constexpr int NCTA   = 740;              // 5 CTAs / SM, one full wave

// ---- shared memory layout (byte offsets) ----
constexpr int SM_BFRAG = 0;              // W2 fp16 fragment table: 4*8*32*8 = 8192 B
constexpr int SM_W1Q   = 8192;           // fp16 W1/b1 col-pair table: 32*16 = 512 B
constexpr int SM_B2T   = 9216;           // b2 fp16x2 fragment table: 128 B
constexpr int SM_WARP  = 9344;           // 4 per-warp Gs16 regions
constexpr int PW       = 4608;           // Gs16: 16 row-pairs x 288 B
constexpr int SMEM_BYTES = SM_WARP + 4 * PW;   // 27776
constexpr int GPS = 288;                 // bytes per interleaved row-pair

__device__ __forceinline__ uint32_t smem_u32(const void* p) {
    uint32_t a;
    asm("{ .reg .u64 t; cvta.to.shared.u64 t, %1; cvt.u32.u64 %0, t; }" : "=r"(a) : "l"(p));
    return a;
}
__device__ __forceinline__ uint32_t pack_h2(__half lo, __half hi) {
    return (uint32_t)__half_as_ushort(lo) | ((uint32_t)__half_as_ushort(hi) << 16);
}
__device__ __forceinline__ uint32_t h2_u32(__half2 h) {
    uint32_t u; memcpy(&u, &h, 4); return u;
}
__device__ __forceinline__ __half2 u32_h2(uint32_t u) {
    __half2 h; memcpy(&h, &u, 4); return h;
}
// fp16-accumulate HMMA: C/D fragment = 2 regs of fp16x2
__device__ __forceinline__ void mma_f16_h(uint32_t* c, const uint32_t* a,
                                          uint32_t b0, uint32_t b1) {
    asm volatile(
        "mma.sync.aligned.m16n8k16.row.col.f16.f16.f16.f16 "
        "{%0,%1}, {%2,%3,%4,%5}, {%6,%7}, {%0,%1};"
        : "+r"(c[0]), "+r"(c[1])
        : "r"(a[0]), "r"(a[1]), "r"(a[2]), "r"(a[3]), "r"(b0), "r"(b1));
}
// one A-fragment reg, entirely in fp16x2:
//   z = rel.W1[:,c0..c0+1] + b1;  leaky = max(z, 0.1*z)
__device__ __forceinline__ uint32_t frag_h(uint32_t rx2, uint32_t ry2, uint32_t rz2,
                                           uint32_t wx, uint32_t wy, uint32_t wz,
                                           uint32_t bb, __half2 c01) {
    __half2 z = __hfma2(u32_h2(rx2), u32_h2(wx),
                __hfma2(u32_h2(ry2), u32_h2(wy),
                __hfma2(u32_h2(rz2), u32_h2(wz), u32_h2(bb))));
    z = __hmax2(z, __hmul2(z, c01));
    return h2_u32(z);
}

} // namespace

// x pre-converted to fp16 (8 MB static scratch; written by cvt_x_kernel)
__device__ __half2 g_xh[(size_t)4 * 16384 * 32];
// pos padded to float4 (1 MB static scratch) -> neighbor gather = 1 LDG.128
__device__ float4 g_pos4[(size_t)4 * 16384];

__global__ void cvt_x_kernel(const float* __restrict__ x) {
    const int i = blockIdx.x * blockDim.x + threadIdx.x;   // 2,097,152 threads
    const float2 v = ((const float2*)x)[i];
    g_xh[i] = __floats2half2_rn(v.x, v.y);
}

__global__ void cvt_pos_kernel(const float* __restrict__ pos) {
    const int i = blockIdx.x * blockDim.x + threadIdx.x;   // 65,536 threads
    g_pos4[i] = make_float4(pos[3 * i], pos[3 * i + 1], pos[3 * i + 2], 0.0f);
}

__global__ void __launch_bounds__(NTHR, 5) pc_mma_kernel(
    const int*   __restrict__ nidx,   // [B, N, 32]
    const float* __restrict__ W1,     // [3, 64]
    const float* __restrict__ b1,     // [64]
    const float* __restrict__ W2,     // [64, 64]
    const float* __restrict__ b2,     // [64]
    float*       __restrict__ out)    // [B, N, 64]
{
    extern __shared__ char smem[];
    const uint32_t sb = smem_u32(smem);

    const int tid  = threadIdx.x;
    const int warp = tid >> 5;
    const int lane = tid & 31;
    const int f0   = 2 * lane;
    const int q    = lane >> 2;       // fragment row base
    const int r    = lane & 3;        // fragment col-pair selector

    // ================= one-time init =================
    // W2'' fp16 fragment table (single plane), entry (s, ni, ln) = 8B {b0, b1}
    for (int i = tid; i < 4 * 8 * 32; i += NTHR) {
        const int s = i >> 8, ni = (i >> 5) & 7, ln = i & 31;
        const int n  = ni * 8 + (ln >> 2);
        const int k0 = s * 16 + (ln & 3) * 2;
        uint2 e;
        e.x = pack_h2(__float2half_rn(W2[k0 * Dc + n]),
                      __float2half_rn(W2[(k0 + 1) * Dc + n]));
        e.y = pack_h2(__float2half_rn(W2[(k0 + 8) * Dc + n]),
                      __float2half_rn(W2[(k0 + 9) * Dc + n]));
        *(uint2*)(smem + SM_BFRAG + (size_t)i * 8) = e;
    }
    // fp16 W1/b1 col-pair table: entry e = (s*2+d)*4 + r, 16B {wx, wy, wz, bb}
    for (int e = tid; e < 32; e += NTHR) {
        const int er = e & 3, ed = (e >> 2) & 1, es = e >> 3;
        const int c0 = 16 * es + 2 * er + 8 * ed;
        uint4 v;
        v.x = pack_h2(__float2half_rn(W1[c0]),          __float2half_rn(W1[c0 + 1]));
        v.y = pack_h2(__float2half_rn(W1[Dc + c0]),     __float2half_rn(W1[Dc + c0 + 1]));
        v.z = pack_h2(__float2half_rn(W1[2 * Dc + c0]), __float2half_rn(W1[2 * Dc + c0 + 1]));
        v.w = pack_h2(__float2half_rn(b1[c0]),          __float2half_rn(b1[c0 + 1]));
        ((uint4*)(smem + SM_W1Q))[e] = v;
    }
    // b2 fp16x2 fragment table: entry (rr, ni) = pack(b2[ni*8+2rr], b2[ni*8+2rr+1])
    for (int e = tid; e < 32; e += NTHR) {
        const int rr = e >> 3, ni = e & 7;
        ((uint32_t*)(smem + SM_B2T))[rr * 8 + ni] =
            pack_h2(__float2half_rn(b2[ni * 8 + 2 * rr]),
                    __float2half_rn(b2[ni * 8 + 2 * rr + 1]));
    }
    __syncthreads();

    // ================= per-lane constants =================
    const uint32_t wbase = sb + SM_WARP + warp * PW;          // Gs16 region
    const uint32_t bfrag_base = sb + SM_BFRAG + (uint32_t)lane * 8u;
    const uint32_t w1q_base = sb + SM_W1Q + (uint32_t)r * 16u;
    const uint32_t b2t_base = sb + SM_B2T + (uint32_t)r * 32u;
    // Gs store base: row-pair interleaved (row -> pair row>>1, parity (row&1)*4)
    const uint32_t gdst0 = wbase + (uint32_t)((q >> 1) * GPS + (q & 1) * 4 + r * 8);
    const uint32_t gsrc  = wbase + (uint32_t)lane * 8u;
    const __half2 c01 = __float2half2_rn(0.1f);

    const int pstride = NCTA * 4;

    // ---- prefetch state for point p ----
    int p = blockIdx.x * 4 + warp;
    int   jv = 0;
    float cxv = 0.f, cyv = 0.f, czv = 0.f, nxv = 0.f, nyv = 0.f, nzv = 0.f;
    if (p < POINTS) {
        const int bb = p >> 14;
        jv  = nidx[(size_t)p * Kc + lane];
        const float4 cp = g_pos4[p];
        const float4 np = g_pos4[bb * Nc + jv];
        cxv = cp.x; cyv = cp.y; czv = cp.z;
        nxv = np.x; nyv = np.y; nzv = np.z;
    }

    for (; p < POINTS; p += pstride) {
        const int b = p >> 14;
        const int j = jv;
        const float rx = cxv - nxv, ry = cyv - nyv, rz = czv - nzv;

        // ---- rel as broadcast fp16x2, for this lane's 4 fragment rows ----
        const uint32_t urx = h2_u32(__float2half2_rn(rx));
        const uint32_t ury = h2_u32(__float2half2_rn(ry));
        const uint32_t urz = h2_u32(__float2half2_rn(rz));
        uint32_t rpx[4], rpy[4], rpz[4];
#pragma unroll
        for (int i = 0; i < 4; ++i) {
            const int src = q + 8 * i;
            rpx[i] = __shfl_sync(0xFFFFFFFFu, urx, src);
            rpy[i] = __shfl_sync(0xFFFFFFFFu, ury, src);
            rpz[i] = __shfl_sync(0xFFFFFFFFu, urz, src);
        }

        // ---- prefetch next point's idx/pos (consumed next iteration) ----
        {
            const int pn = p + pstride;
            if (pn < POINTS) {
                const int bn = pn >> 14;
                jv  = nidx[(size_t)pn * Kc + lane];
                const float4 cp = g_pos4[pn];
                const float4 np = g_pos4[bn * Nc + jv];
                cxv = cp.x; cyv = cp.y; czv = cp.z;
                nxv = np.x; nyv = np.y; nzv = np.z;
            }
        }

        // ---- GEMM (fp16 acc), acc init = b2 -> G' = H*W2 + b2 in fp16x2 ----
        uint32_t acc[32];
        {
            uint32_t bt[8];
            asm("ld.shared.v4.u32 {%0,%1,%2,%3}, [%4];"
                : "=r"(bt[0]), "=r"(bt[1]), "=r"(bt[2]), "=r"(bt[3]) : "r"(b2t_base));
            asm("ld.shared.v4.u32 {%0,%1,%2,%3}, [%4];"
                : "=r"(bt[4]), "=r"(bt[5]), "=r"(bt[6]), "=r"(bt[7]) : "r"(b2t_base + 16));
#pragma unroll
            for (int ni = 0; ni < 8; ++ni) {
                acc[ni * 4 + 0] = bt[ni];
                acc[ni * 4 + 1] = bt[ni];
                acc[ni * 4 + 2] = bt[ni];
                acc[ni * 4 + 3] = bt[ni];
            }
        }

#pragma unroll
        for (int s = 0; s < 4; ++s) {
            uint32_t w0[4], w1r[4];   // d=0 / d=1 col-pair weights {wx,wy,wz,bb}
            const uint32_t qa = w1q_base + (uint32_t)(s * 128);
            asm("ld.shared.v4.u32 {%0,%1,%2,%3}, [%4];"
                : "=r"(w0[0]), "=r"(w0[1]), "=r"(w0[2]), "=r"(w0[3]) : "r"(qa));
            asm("ld.shared.v4.u32 {%0,%1,%2,%3}, [%4];"
                : "=r"(w1r[0]), "=r"(w1r[1]), "=r"(w1r[2]), "=r"(w1r[3]) : "r"(qa + 64));

            uint32_t at0[4], at1[4];
            at0[0] = frag_h(rpx[0], rpy[0], rpz[0], w0[0], w0[1], w0[2], w0[3], c01);
            at0[1] = frag_h(rpx[1], rpy[1], rpz[1], w0[0], w0[1], w0[2], w0[3], c01);
            at0[2] = frag_h(rpx[0], rpy[0], rpz[0], w1r[0], w1r[1], w1r[2], w1r[3], c01);
            at0[3] = frag_h(rpx[1], rpy[1], rpz[1], w1r[0], w1r[1], w1r[2], w1r[3], c01);
            at1[0] = frag_h(rpx[2], rpy[2], rpz[2], w0[0], w0[1], w0[2], w0[3], c01);
            at1[1] = frag_h(rpx[3], rpy[3], rpz[3], w0[0], w0[1], w0[2], w0[3], c01);
            at1[2] = frag_h(rpx[2], rpy[2], rpz[2], w1r[0], w1r[1], w1r[2], w1r[3], c01);
            at1[3] = frag_h(rpx[3], rpy[3], rpz[3], w1r[0], w1r[1], w1r[2], w1r[3], c01);

            const uint32_t bptr = bfrag_base + (uint32_t)s * 2048u;
#pragma unroll
            for (int ni = 0; ni < 8; ++ni) {
                uint32_t h0, h1;
                asm volatile("ld.shared.v2.u32 {%0,%1}, [%2];"
                             : "=r"(h0), "=r"(h1) : "r"(bptr + ni * 256u));
                mma_f16_h(&acc[ni * 4],     at0, h0, h1);
                mma_f16_h(&acc[ni * 4 + 2], at1, h0, h1);
            }
        }

        // ---- transpose G' to pair-interleaved Gs16 (regs already fp16x2) ----
        {
#pragma unroll
            for (int ni = 0; ni < 8; ++ni) {
                const uint32_t a = gdst0 + (uint32_t)(ni * 32);
                asm volatile("st.shared.b32 [%0], %1;" :: "r"(a),               "r"(acc[ni * 4 + 0]));
                asm volatile("st.shared.b32 [%0], %1;" :: "r"(a + 4 * GPS),     "r"(acc[ni * 4 + 1]));
                asm volatile("st.shared.b32 [%0], %1;" :: "r"(a + 8 * GPS),     "r"(acc[ni * 4 + 2]));
                asm volatile("st.shared.b32 [%0], %1;" :: "r"(a + 12 * GPS),    "r"(acc[ni * 4 + 3]));
            }
        }
        __syncwarp();

        // ---- epilogue: out[f] = sum_k G'[k,f] * x_h[j_k, f]  (fp16 product) ----
        const __half2* xhb = g_xh + (size_t)b * Nc * 32;
        float o0 = 0.0f, o1 = 0.0f;
#pragma unroll
        for (int kb = 0; kb < 4; ++kb) {
            __half2 xv[8];
#pragma unroll
            for (int u = 0; u < 8; ++u) {
                const int jk = __shfl_sync(0xFFFFFFFFu, j, kb * 8 + u);
                xv[u] = xhb[(size_t)jk * 32 + lane];
            }
#pragma unroll
            for (int k2 = 0; k2 < 4; ++k2) {
                uint32_t g0, g1;   // rows 8kb + 2k2, 8kb + 2k2 + 1
                asm volatile("ld.shared.v2.u32 {%0,%1}, [%2];"
                             : "=r"(g0), "=r"(g1)
                             : "r"(gsrc + (uint32_t)((kb * 4 + k2) * GPS)));
                const __half2 p0 = __hmul2(u32_h2(g0), xv[k2 * 2]);
                const __half2 p1 = __hmul2(u32_h2(g1), xv[k2 * 2 + 1]);
                const float2 f0v = __half22float2(p0);
                const float2 f1v = __half22float2(p1);
                o0 += f0v.x + f1v.x;
                o1 += f0v.y + f1v.y;
            }
        }
        __syncwarp();   // Gs region reused next iteration

        *(float2*)(out + (size_t)p * Dc + f0) = make_float2(o0, o1);
    }
}

extern "C" void kernel_launch(void* const* d_in, const int* in_sizes, int n_in,
                              void* d_out, int out_size) {
    const float* x    = (const float*)d_in[0];
    const float* pos  = (const float*)d_in[1];
    const int*   nidx = (const int*)  d_in[2];
    const float* W1   = (const float*)d_in[3];
    const float* b1   = (const float*)d_in[4];
    const float* W2   = (const float*)d_in[5];
    const float* b2   = (const float*)d_in[6];
    float* out = (float*)d_out;
    (void)in_sizes; (void)n_in; (void)out_size;

    // x -> fp16 scratch; pos -> float4 scratch (both graph-capturable)
    cvt_x_kernel<<<8192, 256>>>(x);
    cvt_pos_kernel<<<256, 256>>>(pos);

    cudaFuncSetAttribute(pc_mma_kernel, cudaFuncAttributeMaxDynamicSharedMemorySize,
                         SMEM_BYTES);
    pc_mma_kernel<<<NCTA, NTHR, SMEM_BYTES>>>(nidx, W1, b1, W2, b2, out);
}

// round 16
// speedup vs baseline: 1.1365x; 1.0208x over previous
#include <cuda_runtime.h>
#include <cuda_fp16.h>
#include <cstdint>
#include <cstring>
#include <cstddef>

namespace {

constexpr int Nc = 16384, Kc = 32, Dc = 64;
constexpr int POINTS = 4 * Nc;           // 65536
constexpr int NTHR   = 128;              // 4 warps / CTA
constexpr int NCTA   = 740;              // 5 CTAs / SM, one full wave

// ---- shared memory layout (byte offsets) ----
constexpr int SM_BFRAG = 0;              // W2 fp16 fragment table: 4*8*32*8 = 8192 B
constexpr int SM_W1Q   = 8192;           // fp16 W1/b1 col-pair table: 32*16 = 512 B
constexpr int SM_B2T   = 9216;           // b2 fp16x2 fragment table: 128 B
constexpr int SM_WARP  = 9344;           // 4 per-warp Gs16 regions
constexpr int PW       = 4608;           // Gs16: 16 row-pairs x 288 B
constexpr int SMEM_BYTES = SM_WARP + 4 * PW;   // 27776
constexpr int GPS = 288;                 // bytes per interleaved row-pair

__device__ __forceinline__ uint32_t smem_u32(const void* p) {
    uint32_t a;
    asm("{ .reg .u64 t; cvta.to.shared.u64 t, %1; cvt.u32.u64 %0, t; }" : "=r"(a) : "l"(p));
    return a;
}
__device__ __forceinline__ uint32_t pack_h2(__half lo, __half hi) {
    return (uint32_t)__half_as_ushort(lo) | ((uint32_t)__half_as_ushort(hi) << 16);
}
__device__ __forceinline__ uint32_t h2_u32(__half2 h) {
    uint32_t u; memcpy(&u, &h, 4); return u;
}
__device__ __forceinline__ __half2 u32_h2(uint32_t u) {
    __half2 h; memcpy(&h, &u, 4); return h;
}
// fp16-accumulate HMMA, in-place C
__device__ __forceinline__ void mma_f16_h(uint32_t* c, const uint32_t* a,
                                          uint32_t b0, uint32_t b1) {
    asm volatile(
        "mma.sync.aligned.m16n8k16.row.col.f16.f16.f16.f16 "
        "{%0,%1}, {%2,%3,%4,%5}, {%6,%7}, {%0,%1};"
        : "+r"(c[0]), "+r"(c[1])
        : "r"(a[0]), "r"(a[1]), "r"(a[2]), "r"(a[3]), "r"(b0), "r"(b1));
}
// fp16-accumulate HMMA, D != C: initializes the accumulator with C = {cc, cc}
__device__ __forceinline__ void mma_f16_h_init(uint32_t* d, const uint32_t* a,
                                               uint32_t b0, uint32_t b1,
                                               uint32_t cc) {
    asm volatile(
        "mma.sync.aligned.m16n8k16.row.col.f16.f16.f16.f16 "
        "{%0,%1}, {%2,%3,%4,%5}, {%6,%7}, {%8,%8};"
        : "=r"(d[0]), "=r"(d[1])
        : "r"(a[0]), "r"(a[1]), "r"(a[2]), "r"(a[3]), "r"(b0), "r"(b1), "r"(cc));
}
// one A-fragment reg, entirely in fp16x2:
//   z = rel.W1[:,c0..c0+1] + b1;  leaky = max(z, 0.1*z)
__device__ __forceinline__ uint32_t frag_h(uint32_t rx2, uint32_t ry2, uint32_t rz2,
                                           uint32_t wx, uint32_t wy, uint32_t wz,
                                           uint32_t bb, __half2 c01) {
    __half2 z = __hfma2(u32_h2(rx2), u32_h2(wx),
                __hfma2(u32_h2(ry2), u32_h2(wy),
                __hfma2(u32_h2(rz2), u32_h2(wz), u32_h2(bb))));
    z = __hmax2(z, __hmul2(z, c01));
    return h2_u32(z);
}

} // namespace

// x pre-converted to fp16 (8 MB static scratch; written by cvt_x_kernel)
__device__ __half2 g_xh[(size_t)4 * 16384 * 32];
// pos padded to float4 (1 MB static scratch) -> neighbor gather = 1 LDG.128
__device__ float4 g_pos4[(size_t)4 * 16384];

__global__ void cvt_x_kernel(const float* __restrict__ x) {
    const int i = blockIdx.x * blockDim.x + threadIdx.x;   // 2,097,152 threads
    const float2 v = ((const float2*)x)[i];
    g_xh[i] = __floats2half2_rn(v.x, v.y);
}

__global__ void cvt_pos_kernel(const float* __restrict__ pos) {
    const int i = blockIdx.x * blockDim.x + threadIdx.x;   // 65,536 threads
    g_pos4[i] = make_float4(pos[3 * i], pos[3 * i + 1], pos[3 * i + 2], 0.0f);
}

__global__ void __launch_bounds__(NTHR, 5) pc_mma_kernel(
    const int*   __restrict__ nidx,   // [B, N, 32]
    const float* __restrict__ W1,     // [3, 64]
    const float* __restrict__ b1,     // [64]
    const float* __restrict__ W2,     // [64, 64]
    const float* __restrict__ b2,     // [64]
    float*       __restrict__ out)    // [B, N, 64]
{
    extern __shared__ char smem[];
    const uint32_t sb = smem_u32(smem);

    const int tid  = threadIdx.x;
    const int warp = tid >> 5;
    const int lane = tid & 31;
    const int f0   = 2 * lane;
    const int q    = lane >> 2;       // fragment row base
    const int r    = lane & 3;        // fragment col-pair selector

    // ================= one-time init =================
    // W2'' fp16 fragment table (single plane), entry (s, ni, ln) = 8B {b0, b1}
    for (int i = tid; i < 4 * 8 * 32; i += NTHR) {
        const int s = i >> 8, ni = (i >> 5) & 7, ln = i & 31;
        const int n  = ni * 8 + (ln >> 2);
        const int k0 = s * 16 + (ln & 3) * 2;
        uint2 e;
        e.x = pack_h2(__float2half_rn(W2[k0 * Dc + n]),
                      __float2half_rn(W2[(k0 + 1) * Dc + n]));
        e.y = pack_h2(__float2half_rn(W2[(k0 + 8) * Dc + n]),
                      __float2half_rn(W2[(k0 + 9) * Dc + n]));
        *(uint2*)(smem + SM_BFRAG + (size_t)i * 8) = e;
    }
    // fp16 W1/b1 col-pair table: entry e = (s*2+d)*4 + r, 16B {wx, wy, wz, bb}
    for (int e = tid; e < 32; e += NTHR) {
        const int er = e & 3, ed = (e >> 2) & 1, es = e >> 3;
        const int c0 = 16 * es + 2 * er + 8 * ed;
        uint4 v;
        v.x = pack_h2(__float2half_rn(W1[c0]),          __float2half_rn(W1[c0 + 1]));
        v.y = pack_h2(__float2half_rn(W1[Dc + c0]),     __float2half_rn(W1[Dc + c0 + 1]));
        v.z = pack_h2(__float2half_rn(W1[2 * Dc + c0]), __float2half_rn(W1[2 * Dc + c0 + 1]));
        v.w = pack_h2(__float2half_rn(b1[c0]),          __float2half_rn(b1[c0 + 1]));
        ((uint4*)(smem + SM_W1Q))[e] = v;
    }
    // b2 fp16x2 fragment table: entry (rr, ni) = pack(b2[ni*8+2rr], b2[ni*8+2rr+1])
    for (int e = tid; e < 32; e += NTHR) {
        const int rr = e >> 3, ni = e & 7;
        ((uint32_t*)(smem + SM_B2T))[rr * 8 + ni] =
            pack_h2(__float2half_rn(b2[ni * 8 + 2 * rr]),
                    __float2half_rn(b2[ni * 8 + 2 * rr + 1]));
    }
    __syncthreads();

    // ================= per-lane constants =================
    const uint32_t wbase = sb + SM_WARP + warp * PW;          // Gs16 region
    const uint32_t bfrag_base = sb + SM_BFRAG + (uint32_t)lane * 8u;
    const uint32_t w1q_base = sb + SM_W1Q + (uint32_t)r * 16u;
    const uint32_t b2t_base = sb + SM_B2T + (uint32_t)r * 32u;
    // Gs store base: row-pair interleaved (row -> pair row>>1, parity (row&1)*4)
    const uint32_t gdst0 = wbase + (uint32_t)((q >> 1) * GPS + (q & 1) * 4 + r * 8);
    const uint32_t gsrc  = wbase + (uint32_t)lane * 8u;
    const __half2 c01 = __float2half2_rn(0.1f);

    const int pstride = NCTA * 4;

    // ---- prefetch state for point p ----
    int p = blockIdx.x * 4 + warp;
    int   jv = 0;
    float cxv = 0.f, cyv = 0.f, czv = 0.f, nxv = 0.f, nyv = 0.f, nzv = 0.f;
    if (p < POINTS) {
        const int bb = p >> 14;
        jv  = nidx[(size_t)p * Kc + lane];
        const float4 cp = g_pos4[p];
        const float4 np = g_pos4[bb * Nc + jv];
        cxv = cp.x; cyv = cp.y; czv = cp.z;
        nxv = np.x; nyv = np.y; nzv = np.z;
    }

    for (; p < POINTS; p += pstride) {
        const int b = p >> 14;
        const int j = jv;
        const float rx = cxv - nxv, ry = cyv - nyv, rz = czv - nzv;

        // ---- rel as broadcast fp16x2, for this lane's 4 fragment rows ----
        const uint32_t urx = h2_u32(__float2half2_rn(rx));
        const uint32_t ury = h2_u32(__float2half2_rn(ry));
        const uint32_t urz = h2_u32(__float2half2_rn(rz));
        uint32_t rpx[4], rpy[4], rpz[4];
#pragma unroll
        for (int i = 0; i < 4; ++i) {
            const int src = q + 8 * i;
            rpx[i] = __shfl_sync(0xFFFFFFFFu, urx, src);
            rpy[i] = __shfl_sync(0xFFFFFFFFu, ury, src);
            rpz[i] = __shfl_sync(0xFFFFFFFFu, urz, src);
        }

        // ---- prefetch next point's idx/pos (consumed next iteration) ----
        {
            const int pn = p + pstride;
            if (pn < POINTS) {
                const int bn = pn >> 14;
                jv  = nidx[(size_t)pn * Kc + lane];
                const float4 cp = g_pos4[pn];
                const float4 np = g_pos4[bn * Nc + jv];
                cxv = cp.x; cyv = cp.y; czv = cp.z;
                nxv = np.x; nyv = np.y; nzv = np.z;
            }
        }

        // ---- GEMM (fp16 acc); s=0 uses D!=C mma to fold b2 in with no movs ----
        uint32_t acc[32];
        uint32_t bt[8];
        asm("ld.shared.v4.u32 {%0,%1,%2,%3}, [%4];"
            : "=r"(bt[0]), "=r"(bt[1]), "=r"(bt[2]), "=r"(bt[3]) : "r"(b2t_base));
        asm("ld.shared.v4.u32 {%0,%1,%2,%3}, [%4];"
            : "=r"(bt[4]), "=r"(bt[5]), "=r"(bt[6]), "=r"(bt[7]) : "r"(b2t_base + 16));

#pragma unroll
        for (int s = 0; s < 4; ++s) {
            uint32_t w0[4], w1r[4];   // d=0 / d=1 col-pair weights {wx,wy,wz,bb}
            const uint32_t qa = w1q_base + (uint32_t)(s * 128);
            asm("ld.shared.v4.u32 {%0,%1,%2,%3}, [%4];"
                : "=r"(w0[0]), "=r"(w0[1]), "=r"(w0[2]), "=r"(w0[3]) : "r"(qa));
            asm("ld.shared.v4.u32 {%0,%1,%2,%3}, [%4];"
                : "=r"(w1r[0]), "=r"(w1r[1]), "=r"(w1r[2]), "=r"(w1r[3]) : "r"(qa + 64));

            uint32_t at0[4], at1[4];
            at0[0] = frag_h(rpx[0], rpy[0], rpz[0], w0[0], w0[1], w0[2], w0[3], c01);
            at0[1] = frag_h(rpx[1], rpy[1], rpz[1], w0[0], w0[1], w0[2], w0[3], c01);
            at0[2] = frag_h(rpx[0], rpy[0], rpz[0], w1r[0], w1r[1], w1r[2], w1r[3], c01);
            at0[3] = frag_h(rpx[1], rpy[1], rpz[1], w1r[0], w1r[1], w1r[2], w1r[3], c01);
            at1[0] = frag_h(rpx[2], rpy[2], rpz[2], w0[0], w0[1], w0[2], w0[3], c01);
            at1[1] = frag_h(rpx[3], rpy[3], rpz[3], w0[0], w0[1], w0[2], w0[3], c01);
            at1[2] = frag_h(rpx[2], rpy[2], rpz[2], w1r[0], w1r[1], w1r[2], w1r[3], c01);
            at1[3] = frag_h(rpx[3], rpy[3], rpz[3], w1r[0], w1r[1], w1r[2], w1r[3], c01);

            const uint32_t bptr = bfrag_base + (uint32_t)s * 2048u;
#pragma unroll
            for (int ni = 0; ni < 8; ++ni) {
                uint32_t h0, h1;
                asm volatile("ld.shared.v2.u32 {%0,%1}, [%2];"
                             : "=r"(h0), "=r"(h1) : "r"(bptr + ni * 256u));
                if (s == 0) {
                    mma_f16_h_init(&acc[ni * 4],     at0, h0, h1, bt[ni]);
                    mma_f16_h_init(&acc[ni * 4 + 2], at1, h0, h1, bt[ni]);
                } else {
                    mma_f16_h(&acc[ni * 4],     at0, h0, h1);
                    mma_f16_h(&acc[ni * 4 + 2], at1, h0, h1);
                }
            }
        }

        // ---- transpose G' to pair-interleaved Gs16 (regs already fp16x2) ----
        {
#pragma unroll
            for (int ni = 0; ni < 8; ++ni) {
                const uint32_t a = gdst0 + (uint32_t)(ni * 32);
                asm volatile("st.shared.b32 [%0], %1;" :: "r"(a),               "r"(acc[ni * 4 + 0]));
                asm volatile("st.shared.b32 [%0], %1;" :: "r"(a + 4 * GPS),     "r"(acc[ni * 4 + 1]));
                asm volatile("st.shared.b32 [%0], %1;" :: "r"(a + 8 * GPS),     "r"(acc[ni * 4 + 2]));
                asm volatile("st.shared.b32 [%0], %1;" :: "r"(a + 12 * GPS),    "r"(acc[ni * 4 + 3]));
            }
        }
        __syncwarp();

        // ---- epilogue: out[f] = sum_k G'[k,f] * x_h[j_k, f] ----
        // products in fp16, pairwise fp16 add, then f32 accumulate
        const __half2* xhb = g_xh + (size_t)b * Nc * 32;
        float o0 = 0.0f, o1 = 0.0f;
#pragma unroll
        for (int kb = 0; kb < 4; ++kb) {
            __half2 xv[8];
#pragma unroll
            for (int u = 0; u < 8; ++u) {
                const int jk = __shfl_sync(0xFFFFFFFFu, j, kb * 8 + u);
                xv[u] = xhb[(size_t)jk * 32 + lane];
            }
#pragma unroll
            for (int k2 = 0; k2 < 4; ++k2) {
                uint32_t g0, g1;   // rows 8kb + 2k2, 8kb + 2k2 + 1
                asm volatile("ld.shared.v2.u32 {%0,%1}, [%2];"
                             : "=r"(g0), "=r"(g1)
                             : "r"(gsrc + (uint32_t)((kb * 4 + k2) * GPS)));
                const __half2 ps = __hadd2(__hmul2(u32_h2(g0), xv[k2 * 2]),
                                           __hmul2(u32_h2(g1), xv[k2 * 2 + 1]));
                const float2 pf = __half22float2(ps);
                o0 += pf.x;
                o1 += pf.y;
            }
        }
        __syncwarp();   // Gs region reused next iteration

        *(float2*)(out + (size_t)p * Dc + f0) = make_float2(o0, o1);
    }
}

extern "C" void kernel_launch(void* const* d_in, const int* in_sizes, int n_in,
                              void* d_out, int out_size) {
    const float* x    = (const float*)d_in[0];
    const float* pos  = (const float*)d_in[1];
    const int*   nidx = (const int*)  d_in[2];
    const float* W1   = (const float*)d_in[3];
    const float* b1   = (const float*)d_in[4];
    const float* W2   = (const float*)d_in[5];
    const float* b2   = (const float*)d_in[6];
    float* out = (float*)d_out;
    (void)in_sizes; (void)n_in; (void)out_size;

    // x -> fp16 scratch; pos -> float4 scratch (both graph-capturable)
    cvt_x_kernel<<<8192, 256>>>(x);
    cvt_pos_kernel<<<256, 256>>>(pos);

    cudaFuncSetAttribute(pc_mma_kernel, cudaFuncAttributeMaxDynamicSharedMemorySize,
                         SMEM_BYTES);
    pc_mma_kernel<<<NCTA, NTHR, SMEM_BYTES>>>(nidx, W1, b1, W2, b2, out);
}

// round 17
// speedup vs baseline: 1.1880x; 1.0453x over previous
#include <cuda_runtime.h>
#include <cuda_fp16.h>
#include <cstdint>
#include <cstring>
#include <cstddef>

namespace {

constexpr int Nc = 16384, Kc = 32, Dc = 64;
constexpr int POINTS = 4 * Nc;           // 65536
constexpr int NTHR   = 128;              // 4 warps / CTA
constexpr int NCTA   = 740;              // 5 CTAs / SM, one full wave

// ---- shared memory layout (byte offsets) ----
constexpr int SM_BFRAG = 0;              // W2 fp16 fragment table: 4*8*32*8 = 8192 B
constexpr int SM_W1Q   = 8192;           // fp16 W1/b1 col-pair table: 32*16 = 512 B
constexpr int SM_B2T   = 9216;           // b2 fp16x2 fragment table: 128 B
constexpr int SM_WARP  = 9344;           // 4 per-warp regions
constexpr int PW       = 4736;           // Gs16 (16 x 288B) + idx strip (128B)
constexpr int SMEM_BYTES = SM_WARP + 4 * PW;   // 28288
constexpr int GPS = 288;                 // bytes per interleaved row-pair
constexpr int IDX_OFF = 4608;            // idx strip offset inside per-warp region

__device__ __forceinline__ uint32_t smem_u32(const void* p) {
    uint32_t a;
    asm("{ .reg .u64 t; cvta.to.shared.u64 t, %1; cvt.u32.u64 %0, t; }" : "=r"(a) : "l"(p));
    return a;
}
__device__ __forceinline__ uint32_t pack_h2(__half lo, __half hi) {
    return (uint32_t)__half_as_ushort(lo) | ((uint32_t)__half_as_ushort(hi) << 16);
}
__device__ __forceinline__ uint32_t h2_u32(__half2 h) {
    uint32_t u; memcpy(&u, &h, 4); return u;
}
__device__ __forceinline__ __half2 u32_h2(uint32_t u) {
    __half2 h; memcpy(&h, &u, 4); return h;
}
// fp16-accumulate HMMA, in-place C
__device__ __forceinline__ void mma_f16_h(uint32_t* c, const uint32_t* a,
                                          uint32_t b0, uint32_t b1) {
    asm volatile(
        "mma.sync.aligned.m16n8k16.row.col.f16.f16.f16.f16 "
        "{%0,%1}, {%2,%3,%4,%5}, {%6,%7}, {%0,%1};"
        : "+r"(c[0]), "+r"(c[1])
        : "r"(a[0]), "r"(a[1]), "r"(a[2]), "r"(a[3]), "r"(b0), "r"(b1));
}
// fp16-accumulate HMMA, D != C: initializes the accumulator with C = {cc, cc}
__device__ __forceinline__ void mma_f16_h_init(uint32_t* d, const uint32_t* a,
                                               uint32_t b0, uint32_t b1,
                                               uint32_t cc) {
    asm volatile(
        "mma.sync.aligned.m16n8k16.row.col.f16.f16.f16.f16 "
        "{%0,%1}, {%2,%3,%4,%5}, {%6,%7}, {%8,%8};"
        : "=r"(d[0]), "=r"(d[1])
        : "r"(a[0]), "r"(a[1]), "r"(a[2]), "r"(a[3]), "r"(b0), "r"(b1), "r"(cc));
}
// one A-fragment reg, entirely in fp16x2:
//   z = rel.W1[:,c0..c0+1] + b1;  leaky = max(z, 0.1*z)
__device__ __forceinline__ uint32_t frag_h(uint32_t rx2, uint32_t ry2, uint32_t rz2,
                                           uint32_t wx, uint32_t wy, uint32_t wz,
                                           uint32_t bb, __half2 c01) {
    __half2 z = __hfma2(u32_h2(rx2), u32_h2(wx),
                __hfma2(u32_h2(ry2), u32_h2(wy),
                __hfma2(u32_h2(rz2), u32_h2(wz), u32_h2(bb))));
    z = __hmax2(z, __hmul2(z, c01));
    return h2_u32(z);
}

} // namespace

// x pre-converted to fp16 (8 MB static scratch)
__device__ __half2 g_xh[(size_t)4 * 16384 * 32];
// pos padded to float4 (1 MB static scratch) -> neighbor gather = 1 LDG.128
__device__ float4 g_pos4[(size_t)4 * 16384];

// fused converter: x -> fp16 (vectorized, 4 half2/thread) and pos -> float4
__global__ void __launch_bounds__(256) cvt_kernel(const float* __restrict__ x,
                                                  const float* __restrict__ pos) {
    const int tid = blockIdx.x * blockDim.x + threadIdx.x;   // 524288 threads
    // x: 1,048,576 float4 reads -> 2 per thread
#pragma unroll
    for (int it = 0; it < 2; ++it) {
        const int i = tid + it * 524288;
        const float4 v = ((const float4*)x)[i];
        uint2 o;
        o.x = h2_u32(__floats2half2_rn(v.x, v.y));
        o.y = h2_u32(__floats2half2_rn(v.z, v.w));
        ((uint2*)g_xh)[i] = o;
    }
    // pos: 65,536 entries -> first 1/8 of threads
    if (tid < 65536) {
        g_pos4[tid] = make_float4(pos[3 * tid], pos[3 * tid + 1],
                                  pos[3 * tid + 2], 0.0f);
    }
}

__global__ void __launch_bounds__(NTHR, 5) pc_mma_kernel(
    const int*   __restrict__ nidx,   // [B, N, 32]
    const float* __restrict__ W1,     // [3, 64]
    const float* __restrict__ b1,     // [64]
    const float* __restrict__ W2,     // [64, 64]
    const float* __restrict__ b2,     // [64]
    float*       __restrict__ out)    // [B, N, 64]
{
    extern __shared__ char smem[];
    const uint32_t sb = smem_u32(smem);

    const int tid  = threadIdx.x;
    const int warp = tid >> 5;
    const int lane = tid & 31;
    const int f0   = 2 * lane;
    const int q    = lane >> 2;       // fragment row base
    const int r    = lane & 3;        // fragment col-pair selector

    // ================= one-time init =================
    // W2'' fp16 fragment table (single plane), entry (s, ni, ln) = 8B {b0, b1}
    for (int i = tid; i < 4 * 8 * 32; i += NTHR) {
        const int s = i >> 8, ni = (i >> 5) & 7, ln = i & 31;
        const int n  = ni * 8 + (ln >> 2);
        const int k0 = s * 16 + (ln & 3) * 2;
        uint2 e;
        e.x = pack_h2(__float2half_rn(W2[k0 * Dc + n]),
                      __float2half_rn(W2[(k0 + 1) * Dc + n]));
        e.y = pack_h2(__float2half_rn(W2[(k0 + 8) * Dc + n]),
                      __float2half_rn(W2[(k0 + 9) * Dc + n]));
        *(uint2*)(smem + SM_BFRAG + (size_t)i * 8) = e;
    }
    // fp16 W1/b1 col-pair table: entry e = (s*2+d)*4 + r, 16B {wx, wy, wz, bb}
    for (int e = tid; e < 32; e += NTHR) {
        const int er = e & 3, ed = (e >> 2) & 1, es = e >> 3;
        const int c0 = 16 * es + 2 * er + 8 * ed;
        uint4 v;
        v.x = pack_h2(__float2half_rn(W1[c0]),          __float2half_rn(W1[c0 + 1]));
        v.y = pack_h2(__float2half_rn(W1[Dc + c0]),     __float2half_rn(W1[Dc + c0 + 1]));
        v.z = pack_h2(__float2half_rn(W1[2 * Dc + c0]), __float2half_rn(W1[2 * Dc + c0 + 1]));
        v.w = pack_h2(__float2half_rn(b1[c0]),          __float2half_rn(b1[c0 + 1]));
        ((uint4*)(smem + SM_W1Q))[e] = v;
    }
    // b2 fp16x2 fragment table: entry (rr, ni) = pack(b2[ni*8+2rr], b2[ni*8+2rr+1])
    for (int e = tid; e < 32; e += NTHR) {
        const int rr = e >> 3, ni = e & 7;
        ((uint32_t*)(smem + SM_B2T))[rr * 8 + ni] =
            pack_h2(__float2half_rn(b2[ni * 8 + 2 * rr]),
                    __float2half_rn(b2[ni * 8 + 2 * rr + 1]));
    }
    __syncthreads();

    // ================= per-lane constants =================
    const uint32_t wbase = sb + SM_WARP + warp * PW;          // Gs16 region
    const uint32_t bfrag_base = sb + SM_BFRAG + (uint32_t)lane * 8u;
    const uint32_t w1q_base = sb + SM_W1Q + (uint32_t)r * 16u;
    const uint32_t b2t_base = sb + SM_B2T + (uint32_t)r * 32u;
    // Gs store base: row-pair interleaved (row -> pair row>>1, parity (row&1)*4)
    const uint32_t gdst0 = wbase + (uint32_t)((q >> 1) * GPS + (q & 1) * 4 + r * 8);
    const uint32_t gsrc  = wbase + (uint32_t)lane * 8u;
    const uint32_t idxs  = wbase + IDX_OFF;                   // j strip (128 B)
    const __half2 c01 = __float2half2_rn(0.1f);

    const int pstride = NCTA * 4;

    // ---- prefetch state for point p ----
    int p = blockIdx.x * 4 + warp;
    int   jv = 0;
    float cxv = 0.f, cyv = 0.f, czv = 0.f, nxv = 0.f, nyv = 0.f, nzv = 0.f;
    if (p < POINTS) {
        const int bb = p >> 14;
        jv  = nidx[(size_t)p * Kc + lane];
        const float4 cp = g_pos4[p];
        const float4 np = g_pos4[bb * Nc + jv];
        cxv = cp.x; cyv = cp.y; czv = cp.z;
        nxv = np.x; nyv = np.y; nzv = np.z;
    }

    for (; p < POINTS; p += pstride) {
        const int b = p >> 14;
        const float rx = cxv - nxv, ry = cyv - nyv, rz = czv - nzv;

        // publish this point's j to the per-warp idx strip
        asm volatile("st.shared.b32 [%0], %1;"
                     :: "r"(idxs + (uint32_t)lane * 4u), "r"(jv));

        // ---- rel as broadcast fp16x2, for this lane's 4 fragment rows ----
        const uint32_t urx = h2_u32(__float2half2_rn(rx));
        const uint32_t ury = h2_u32(__float2half2_rn(ry));
        const uint32_t urz = h2_u32(__float2half2_rn(rz));
        uint32_t rpx[4], rpy[4], rpz[4];
#pragma unroll
        for (int i = 0; i < 4; ++i) {
            const int src = q + 8 * i;
            rpx[i] = __shfl_sync(0xFFFFFFFFu, urx, src);
            rpy[i] = __shfl_sync(0xFFFFFFFFu, ury, src);
            rpz[i] = __shfl_sync(0xFFFFFFFFu, urz, src);
        }

        // ---- prefetch next point's idx/pos (consumed next iteration) ----
        {
            const int pn = p + pstride;
            if (pn < POINTS) {
                const int bn = pn >> 14;
                jv  = nidx[(size_t)pn * Kc + lane];
                const float4 cp = g_pos4[pn];
                const float4 np = g_pos4[bn * Nc + jv];
                cxv = cp.x; cyv = cp.y; czv = cp.z;
                nxv = np.x; nyv = np.y; nzv = np.z;
            }
        }

        // ---- GEMM (fp16 acc); s=0 uses D!=C mma to fold b2 in with no movs ----
        uint32_t acc[32];
        uint32_t bt[8];
        asm("ld.shared.v4.u32 {%0,%1,%2,%3}, [%4];"
            : "=r"(bt[0]), "=r"(bt[1]), "=r"(bt[2]), "=r"(bt[3]) : "r"(b2t_base));
        asm("ld.shared.v4.u32 {%0,%1,%2,%3}, [%4];"
            : "=r"(bt[4]), "=r"(bt[5]), "=r"(bt[6]), "=r"(bt[7]) : "r"(b2t_base + 16));

#pragma unroll
        for (int s = 0; s < 4; ++s) {
            uint32_t w0[4], w1r[4];   // d=0 / d=1 col-pair weights {wx,wy,wz,bb}
            const uint32_t qa = w1q_base + (uint32_t)(s * 128);
            asm("ld.shared.v4.u32 {%0,%1,%2,%3}, [%4];"
                : "=r"(w0[0]), "=r"(w0[1]), "=r"(w0[2]), "=r"(w0[3]) : "r"(qa));
            asm("ld.shared.v4.u32 {%0,%1,%2,%3}, [%4];"
                : "=r"(w1r[0]), "=r"(w1r[1]), "=r"(w1r[2]), "=r"(w1r[3]) : "r"(qa + 64));

            uint32_t at0[4], at1[4];
            at0[0] = frag_h(rpx[0], rpy[0], rpz[0], w0[0], w0[1], w0[2], w0[3], c01);
            at0[1] = frag_h(rpx[1], rpy[1], rpz[1], w0[0], w0[1], w0[2], w0[3], c01);
            at0[2] = frag_h(rpx[0], rpy[0], rpz[0], w1r[0], w1r[1], w1r[2], w1r[3], c01);
            at0[3] = frag_h(rpx[1], rpy[1], rpz[1], w1r[0], w1r[1], w1r[2], w1r[3], c01);
            at1[0] = frag_h(rpx[2], rpy[2], rpz[2], w0[0], w0[1], w0[2], w0[3], c01);
            at1[1] = frag_h(rpx[3], rpy[3], rpz[3], w0[0], w0[1], w0[2], w0[3], c01);
            at1[2] = frag_h(rpx[2], rpy[2], rpz[2], w1r[0], w1r[1], w1r[2], w1r[3], c01);
            at1[3] = frag_h(rpx[3], rpy[3], rpz[3], w1r[0], w1r[1], w1r[2], w1r[3], c01);

            const uint32_t bptr = bfrag_base + (uint32_t)s * 2048u;
#pragma unroll
            for (int ni = 0; ni < 8; ++ni) {
                uint32_t h0, h1;
                asm volatile("ld.shared.v2.u32 {%0,%1}, [%2];"
                             : "=r"(h0), "=r"(h1) : "r"(bptr + ni * 256u));
                if (s == 0) {
                    mma_f16_h_init(&acc[ni * 4],     at0, h0, h1, bt[ni]);
                    mma_f16_h_init(&acc[ni * 4 + 2], at1, h0, h1, bt[ni]);
                } else {
                    mma_f16_h(&acc[ni * 4],     at0, h0, h1);
                    mma_f16_h(&acc[ni * 4 + 2], at1, h0, h1);
                }
            }
        }

        // ---- transpose G' to pair-interleaved Gs16 (regs already fp16x2) ----
        {
#pragma unroll
            for (int ni = 0; ni < 8; ++ni) {
                const uint32_t a = gdst0 + (uint32_t)(ni * 32);
                asm volatile("st.shared.b32 [%0], %1;" :: "r"(a),               "r"(acc[ni * 4 + 0]));
                asm volatile("st.shared.b32 [%0], %1;" :: "r"(a + 4 * GPS),     "r"(acc[ni * 4 + 1]));
                asm volatile("st.shared.b32 [%0], %1;" :: "r"(a + 8 * GPS),     "r"(acc[ni * 4 + 2]));
                asm volatile("st.shared.b32 [%0], %1;" :: "r"(a + 12 * GPS),    "r"(acc[ni * 4 + 3]));
            }
        }
        __syncwarp();

        // ---- epilogue: out[f] = sum_k G'[k,f] * x_h[j_k, f] ----
        // j values from the smem strip (4 per LDS.128), products fp16,
        // pairwise fp16 add, then f32 accumulate
        const __half2* xhb = g_xh + (size_t)b * Nc * 32;
        float o0 = 0.0f, o1 = 0.0f;
#pragma unroll
        for (int kb = 0; kb < 4; ++kb) {
            int j4a[4], j4b[4];
            asm volatile("ld.shared.v4.u32 {%0,%1,%2,%3}, [%4];"
                         : "=r"(j4a[0]), "=r"(j4a[1]), "=r"(j4a[2]), "=r"(j4a[3])
                         : "r"(idxs + (uint32_t)(kb * 32)));
            asm volatile("ld.shared.v4.u32 {%0,%1,%2,%3}, [%4];"
                         : "=r"(j4b[0]), "=r"(j4b[1]), "=r"(j4b[2]), "=r"(j4b[3])
                         : "r"(idxs + (uint32_t)(kb * 32 + 16)));
            __half2 xv[8];
#pragma unroll
            for (int u = 0; u < 4; ++u) {
                xv[u]     = xhb[(size_t)j4a[u] * 32 + lane];
                xv[u + 4] = xhb[(size_t)j4b[u] * 32 + lane];
            }
#pragma unroll
            for (int k2 = 0; k2 < 4; ++k2) {
                uint32_t g0, g1;   // rows 8kb + 2k2, 8kb + 2k2 + 1
                asm volatile("ld.shared.v2.u32 {%0,%1}, [%2];"
                             : "=r"(g0), "=r"(g1)
                             : "r"(gsrc + (uint32_t)((kb * 4 + k2) * GPS)));
                const __half2 ps = __hadd2(__hmul2(u32_h2(g0), xv[k2 * 2]),
                                           __hmul2(u32_h2(g1), xv[k2 * 2 + 1]));
                const float2 pf = __half22float2(ps);
                o0 += pf.x;
                o1 += pf.y;
            }
        }
        __syncwarp();   // Gs + idx regions reused next iteration

        *(float2*)(out + (size_t)p * Dc + f0) = make_float2(o0, o1);
    }
}

extern "C" void kernel_launch(void* const* d_in, const int* in_sizes, int n_in,
                              void* d_out, int out_size) {
    const float* x    = (const float*)d_in[0];
    const float* pos  = (const float*)d_in[1];
    const int*   nidx = (const int*)  d_in[2];
    const float* W1   = (const float*)d_in[3];
    const float* b1   = (const float*)d_in[4];
    const float* W2   = (const float*)d_in[5];
    const float* b2   = (const float*)d_in[6];
    float* out = (float*)d_out;
    (void)in_sizes; (void)n_in; (void)out_size;

    // fused x -> fp16 + pos -> float4 (vectorized; graph-capturable)
    cvt_kernel<<<2048, 256>>>(x, pos);

    cudaFuncSetAttribute(pc_mma_kernel, cudaFuncAttributeMaxDynamicSharedMemorySize,
                         SMEM_BYTES);
    pc_mma_kernel<<<NCTA, NTHR, SMEM_BYTES>>>(nidx, W1, b1, W2, b2, out);
}